// round 5
// baseline (speedup 1.0000x reference)
#include <cuda_runtime.h>

#define N_NODES 50000
#define N_EDGES 800000
#define IN_F 96
#define HID 64
#define N_CLS 32

// Scratch (zero-initialized at module load; every launch leaves them zeroed
// again, so graph replays stay deterministic without a memset pass).
__device__ __align__(256) float g_aggx[N_NODES * IN_F];  // 19.2 MB
__device__ __align__(256) float g_aggh[N_NODES * HID];   // 12.8 MB
__device__ __align__(256) float g_h   [N_NODES * HID];   // 12.8 MB

__device__ __forceinline__ void red_add_v4(float* addr, float4 v) {
    asm volatile("red.global.add.v4.f32 [%0], {%1,%2,%3,%4};"
                 :: "l"(addr), "f"(v.x), "f"(v.y), "f"(v.z), "f"(v.w)
                 : "memory");
}

// ---------------------------------------------------------------------------
// Layer-1 edge pass: g_aggx[dst] += x[src]   (96 floats = 24 float4 per edge)
// One warp per edge; lanes 0..23 each move one float4.
// edge_index is int32 (JAX downcasts int64 -> int32 without x64 mode).
// ---------------------------------------------------------------------------
__global__ __launch_bounds__(256) void scatter_x_kernel(
    const float* __restrict__ x, const int* __restrict__ ei)
{
    int warp = (blockIdx.x * blockDim.x + threadIdx.x) >> 5;
    int lane = threadIdx.x & 31;
    if (warp >= N_EDGES) return;
    int s = ei[warp];
    int d = ei[N_EDGES + warp];
    if (lane < 24) {
        const float4* srow = reinterpret_cast<const float4*>(x + (size_t)s * IN_F);
        float4 v = __ldg(srow + lane);
        red_add_v4(g_aggx + (size_t)d * IN_F + lane * 4, v);
    }
}

// ---------------------------------------------------------------------------
// Layer-2 edge pass: g_aggh[dst] += g_h[src]  (64 floats = 16 float4 per edge)
// Half-warp per edge.
// ---------------------------------------------------------------------------
__global__ __launch_bounds__(256) void scatter_h_kernel(
    const int* __restrict__ ei)
{
    int t = blockIdx.x * blockDim.x + threadIdx.x;
    int e = t >> 4;
    int lane = t & 15;
    if (e >= N_EDGES) return;
    int s = ei[e];
    int d = ei[N_EDGES + e];
    float4 v = *reinterpret_cast<const float4*>(g_h + (size_t)s * HID + lane * 4);
    red_add_v4(g_aggh + (size_t)d * HID + lane * 4, v);
}

// ---------------------------------------------------------------------------
// Layer-1 node GEMM: H = relu(AggX @ W1 + b1), warp-per-row.
// W1 [96,64] row-major lives in smem (24 KB). Row held in 3 regs/lane,
// broadcast by shfl. Also re-zeros the AggX row it consumed.
// ---------------------------------------------------------------------------
__global__ __launch_bounds__(256) void gemm1_kernel(
    const float* __restrict__ W1, const float* __restrict__ b1)
{
    __shared__ float Ws[IN_F * HID];
    __shared__ float bs[HID];
    int tid = threadIdx.x;
    for (int i = tid; i < IN_F * HID; i += 256) Ws[i] = W1[i];
    if (tid < HID) bs[tid] = b1[tid];
    __syncthreads();

    int warp = tid >> 5, lane = tid & 31;
    int row = blockIdx.x * 8 + warp;
    if (row >= N_NODES) return;

    float* arow = g_aggx + (size_t)row * IN_F;
    float r0 = arow[lane], r1 = arow[lane + 32], r2 = arow[lane + 64];

    float accx = 0.f, accy = 0.f;
#pragma unroll
    for (int k = 0; k < IN_F; k++) {
        float src = (k < 32) ? r0 : ((k < 64) ? r1 : r2);
        float v = __shfl_sync(0xffffffffu, src, k & 31);
        float2 w = *reinterpret_cast<const float2*>(Ws + k * HID + 2 * lane);
        accx = fmaf(v, w.x, accx);
        accy = fmaf(v, w.y, accy);
    }
    // reset accumulator row for the next graph replay
    arow[lane] = 0.f; arow[lane + 32] = 0.f; arow[lane + 64] = 0.f;

    float2 o;
    o.x = fmaxf(accx + bs[2 * lane], 0.f);
    o.y = fmaxf(accy + bs[2 * lane + 1], 0.f);
    *reinterpret_cast<float2*>(g_h + (size_t)row * HID + 2 * lane) = o;
}

// ---------------------------------------------------------------------------
// Layer-2 node GEMM + bias + log_softmax, warp-per-row (lane == class).
// Also re-zeros the AggH row it consumed.
// ---------------------------------------------------------------------------
__global__ __launch_bounds__(256) void gemm2_kernel(
    const float* __restrict__ W2, const float* __restrict__ b2,
    float* __restrict__ out)
{
    __shared__ float Ws[HID * N_CLS];
    __shared__ float bs[N_CLS];
    int tid = threadIdx.x;
    for (int i = tid; i < HID * N_CLS; i += 256) Ws[i] = W2[i];
    if (tid < N_CLS) bs[tid] = b2[tid];
    __syncthreads();

    int warp = tid >> 5, lane = tid & 31;
    int row = blockIdx.x * 8 + warp;
    if (row >= N_NODES) return;

    float* arow = g_aggh + (size_t)row * HID;
    float r0 = arow[lane], r1 = arow[lane + 32];

    float acc = 0.f;
#pragma unroll
    for (int k = 0; k < HID; k++) {
        float src = (k < 32) ? r0 : r1;
        float v = __shfl_sync(0xffffffffu, src, k & 31);
        acc = fmaf(v, Ws[k * N_CLS + lane], acc);
    }
    arow[lane] = 0.f; arow[lane + 32] = 0.f;

    acc += bs[lane];
    float m = acc;
#pragma unroll
    for (int o = 16; o; o >>= 1) m = fmaxf(m, __shfl_xor_sync(0xffffffffu, m, o));
    float e = expf(acc - m);
    float s = e;
#pragma unroll
    for (int o = 16; o; o >>= 1) s += __shfl_xor_sync(0xffffffffu, s, o);
    out[(size_t)row * N_CLS + lane] = (acc - m) - logf(s);
}

// ---------------------------------------------------------------------------
extern "C" void kernel_launch(void* const* d_in, const int* in_sizes, int n_in,
                              void* d_out, int out_size)
{
    const float* x  = (const float*)d_in[0];
    const int*   ei = (const int*)d_in[1];   // int32 edge index (JAX x64 off)
    const float* W1 = (const float*)d_in[2];
    const float* b1 = (const float*)d_in[3];
    const float* W2 = (const float*)d_in[4];
    const float* b2 = (const float*)d_in[5];
    float* out = (float*)d_out;

    // warp per edge (8 edges / 256-thread block)
    scatter_x_kernel<<<(N_EDGES + 7) / 8, 256>>>(x, ei);
    // warp per row (8 rows / block)
    gemm1_kernel<<<(N_NODES + 7) / 8, 256>>>(W1, b1);
    // half-warp per edge (16 edges / block)
    scatter_h_kernel<<<(N_EDGES + 15) / 16, 256>>>(ei);
    gemm2_kernel<<<(N_NODES + 7) / 8, 256>>>(W2, b2, out);
}

// round 6
// speedup vs baseline: 1.9418x; 1.9418x over previous
#include <cuda_runtime.h>

#define N_NODES 50000
#define N_EDGES 800000
#define IN_F 96
#define HID 64
#define N_CLS 32

#define SCAN_B 1024
#define NSCAN_BLOCKS ((N_NODES + SCAN_B - 1) / SCAN_B)   // 49

// ---------------------------------------------------------------------------
// Scratch. All fully overwritten (or zeroed+reused) every launch -> graph
// replays are deterministic. Total ~16.3 MB; whole working set ~42 MB << L2.
// ---------------------------------------------------------------------------
__device__ __align__(256) int   g_cnt [N_NODES];        // counts, then cursors
__device__ __align__(256) int   g_off [N_NODES + 1];    // CSR offsets (by dst)
__device__ __align__(256) int   g_srcs[N_EDGES];        // src ids bucketed by dst
__device__ __align__(256) int   g_bsum[NSCAN_BLOCKS + 1];
__device__ __align__(256) float g_h   [N_NODES * HID];  // layer-1 output

// ============================ CSR build ====================================

__global__ __launch_bounds__(256) void zero_cnt_kernel()
{
    int i = blockIdx.x * 256 + threadIdx.x;
    if (i < N_NODES) g_cnt[i] = 0;
}

__global__ __launch_bounds__(256) void count_kernel(const int* __restrict__ ei)
{
    int e = blockIdx.x * 256 + threadIdx.x;
    if (e < N_EDGES) atomicAdd(&g_cnt[ei[N_EDGES + e]], 1);
}

// Per-block inclusive scan (Hillis-Steele); writes block-exclusive prefix and
// per-block totals.
__global__ __launch_bounds__(SCAN_B) void scan_block_kernel()
{
    __shared__ int sd[SCAN_B];
    int t = threadIdx.x;
    int idx = blockIdx.x * SCAN_B + t;
    int v = (idx < N_NODES) ? g_cnt[idx] : 0;
    sd[t] = v;
    __syncthreads();
#pragma unroll
    for (int ofs = 1; ofs < SCAN_B; ofs <<= 1) {
        int add = (t >= ofs) ? sd[t - ofs] : 0;
        __syncthreads();
        sd[t] += add;
        __syncthreads();
    }
    if (idx < N_NODES) g_off[idx] = sd[t] - v;            // exclusive within block
    if (t == SCAN_B - 1) g_bsum[blockIdx.x] = sd[t];      // block total
}

// Scan the 49 block totals (single block).
__global__ __launch_bounds__(64) void scan_tops_kernel()
{
    __shared__ int sd[64];
    int t = threadIdx.x;
    int v = (t < NSCAN_BLOCKS) ? g_bsum[t] : 0;
    sd[t] = v;
    __syncthreads();
#pragma unroll
    for (int ofs = 1; ofs < 64; ofs <<= 1) {
        int add = (t >= ofs) ? sd[t - ofs] : 0;
        __syncthreads();
        sd[t] += add;
        __syncthreads();
    }
    if (t < NSCAN_BLOCKS) g_bsum[t] = sd[t] - v;          // exclusive block base
}

// Add block bases; init cursors; set final offset.
__global__ __launch_bounds__(256) void add_base_kernel()
{
    int i = blockIdx.x * 256 + threadIdx.x;
    if (i < N_NODES) {
        int o = g_off[i] + g_bsum[i >> 10];
        g_off[i] = o;
        g_cnt[i] = o;                                     // cursor for fill
    }
    if (i == 0) g_off[N_NODES] = N_EDGES;
}

__global__ __launch_bounds__(256) void fill_kernel(const int* __restrict__ ei)
{
    int e = blockIdx.x * 256 + threadIdx.x;
    if (e < N_EDGES) {
        int d = ei[N_EDGES + e];
        int p = atomicAdd(&g_cnt[d], 1);
        g_srcs[p] = ei[e];
    }
}

// ====================== Layer 1: gather + GEMM + relu ======================
// 32 nodes / block (256 threads). Warp w aggregates nodes w*4..w*4+3 into
// smem As (row stride 100 floats: float4-aligned, banks spread). Then the
// block does the 32x96 @ 96x64 GEMM: thread owns one column and 8 rows, so
// each W smem read is amortized across 8 register accumulators.
// ---------------------------------------------------------------------------
#define L1_ROWS 32
#define L1_STRIDE 100

__global__ __launch_bounds__(256) void layer1_kernel(
    const float* __restrict__ x,
    const float* __restrict__ W1, const float* __restrict__ b1)
{
    __shared__ float As[L1_ROWS][L1_STRIDE];
    __shared__ float Ws[IN_F * HID];
    __shared__ float bs[HID];

    int tid  = threadIdx.x;
    int warp = tid >> 5, lane = tid & 31;
    int base = blockIdx.x * L1_ROWS;

    for (int i = tid; i < IN_F * HID; i += 256) Ws[i] = W1[i];
    if (tid < HID) bs[tid] = b1[tid];

    // ---- aggregation: warp per node, 4 nodes per warp ----
    for (int i = 0; i < 4; i++) {
        int r = warp * 4 + i;
        int node = base + r;
        float r0 = 0.f, r1 = 0.f, r2 = 0.f;
        if (node < N_NODES) {
            int e0 = g_off[node], e1 = g_off[node + 1];
            for (int e = e0; e < e1; e++) {
                int s = g_srcs[e];
                const float* xp = x + (size_t)s * IN_F;
                r0 += xp[lane];
                r1 += xp[lane + 32];
                r2 += xp[lane + 64];
            }
        }
        As[r][lane]      = r0;
        As[r][lane + 32] = r1;
        As[r][lane + 64] = r2;
    }
    __syncthreads();

    // ---- GEMM: thread t -> column c = t&63, rows rb*8 .. rb*8+7 ----
    int c  = tid & 63;
    int rb = tid >> 6;          // 0..3
    float acc[8];
#pragma unroll
    for (int r = 0; r < 8; r++) acc[r] = 0.f;

#pragma unroll
    for (int kc = 0; kc < IN_F / 4; kc++) {
        int k = kc * 4;
        float w0 = Ws[(k + 0) * HID + c];
        float w1 = Ws[(k + 1) * HID + c];
        float w2 = Ws[(k + 2) * HID + c];
        float w3 = Ws[(k + 3) * HID + c];
#pragma unroll
        for (int r = 0; r < 8; r++) {
            float4 a = *reinterpret_cast<const float4*>(&As[rb * 8 + r][k]);
            acc[r] = fmaf(a.x, w0, fmaf(a.y, w1, fmaf(a.z, w2, fmaf(a.w, w3, acc[r]))));
        }
    }

    float bias = bs[c];
#pragma unroll
    for (int r = 0; r < 8; r++) {
        int row = base + rb * 8 + r;
        if (row < N_NODES)
            g_h[(size_t)row * HID + c] = fmaxf(acc[r] + bias, 0.f);
    }
}

// ============ Layer 2: gather + GEMM + bias + log_softmax ==================
// Same structure; 32 nodes/block. GEMM 32x64 @ 64x32; thread owns column
// c = lane (== class) and 4 rows, so each warp holds all 32 classes of its
// rows -> softmax reductions are warp-local shfl_xor.
// ---------------------------------------------------------------------------
#define L2_STRIDE 68

__global__ __launch_bounds__(256) void layer2_kernel(
    const float* __restrict__ W2, const float* __restrict__ b2,
    float* __restrict__ out)
{
    __shared__ float As[L1_ROWS][L2_STRIDE];
    __shared__ float Ws[HID * N_CLS];
    __shared__ float bs[N_CLS];

    int tid  = threadIdx.x;
    int warp = tid >> 5, lane = tid & 31;
    int base = blockIdx.x * L1_ROWS;

    for (int i = tid; i < HID * N_CLS; i += 256) Ws[i] = W2[i];
    if (tid < N_CLS) bs[tid] = b2[tid];

    // ---- aggregation: warp per node, 4 nodes per warp ----
    for (int i = 0; i < 4; i++) {
        int r = warp * 4 + i;
        int node = base + r;
        float r0 = 0.f, r1 = 0.f;
        if (node < N_NODES) {
            int e0 = g_off[node], e1 = g_off[node + 1];
            for (int e = e0; e < e1; e++) {
                int s = g_srcs[e];
                const float* hp = g_h + (size_t)s * HID;
                r0 += hp[lane];
                r1 += hp[lane + 32];
            }
        }
        As[r][lane]      = r0;
        As[r][lane + 32] = r1;
    }
    __syncthreads();

    // ---- GEMM: thread -> class c = lane, rows warp*4 .. warp*4+3 ----
    int c  = lane;
    int rb = warp;              // 0..7
    float acc[4];
#pragma unroll
    for (int r = 0; r < 4; r++) acc[r] = 0.f;

#pragma unroll
    for (int kc = 0; kc < HID / 4; kc++) {
        int k = kc * 4;
        float w0 = Ws[(k + 0) * N_CLS + c];
        float w1 = Ws[(k + 1) * N_CLS + c];
        float w2 = Ws[(k + 2) * N_CLS + c];
        float w3 = Ws[(k + 3) * N_CLS + c];
#pragma unroll
        for (int r = 0; r < 4; r++) {
            float4 a = *reinterpret_cast<const float4*>(&As[rb * 4 + r][k]);
            acc[r] = fmaf(a.x, w0, fmaf(a.y, w1, fmaf(a.z, w2, fmaf(a.w, w3, acc[r]))));
        }
    }

    float bias = bs[c];
#pragma unroll
    for (int r = 0; r < 4; r++) {
        int row = base + rb * 4 + r;
        float v = acc[r] + bias;
        float m = v;
#pragma unroll
        for (int o = 16; o; o >>= 1) m = fmaxf(m, __shfl_xor_sync(0xffffffffu, m, o));
        float e = __expf(v - m);
        float s = e;
#pragma unroll
        for (int o = 16; o; o >>= 1) s += __shfl_xor_sync(0xffffffffu, s, o);
        if (row < N_NODES)
            out[(size_t)row * N_CLS + c] = (v - m) - __logf(s);
    }
}

// ---------------------------------------------------------------------------
extern "C" void kernel_launch(void* const* d_in, const int* in_sizes, int n_in,
                              void* d_out, int out_size)
{
    const float* x  = (const float*)d_in[0];
    const int*   ei = (const int*)d_in[1];   // int32 edge index (JAX x64 off)
    const float* W1 = (const float*)d_in[2];
    const float* b1 = (const float*)d_in[3];
    const float* W2 = (const float*)d_in[4];
    const float* b2 = (const float*)d_in[5];
    float* out = (float*)d_out;

    const int NODE_BLKS = (N_NODES + 255) / 256;
    const int EDGE_BLKS = (N_EDGES + 255) / 256;
    const int TILE_BLKS = (N_NODES + L1_ROWS - 1) / L1_ROWS;

    // CSR build (per launch; edge_index is an input, so this must be in-graph)
    zero_cnt_kernel  <<<NODE_BLKS, 256>>>();
    count_kernel     <<<EDGE_BLKS, 256>>>(ei);
    scan_block_kernel<<<NSCAN_BLOCKS, SCAN_B>>>();
    scan_tops_kernel <<<1, 64>>>();
    add_base_kernel  <<<NODE_BLKS, 256>>>();
    fill_kernel      <<<EDGE_BLKS, 256>>>(ei);

    // Fused layers
    layer1_kernel<<<TILE_BLKS, 256>>>(x, W1, b1);
    layer2_kernel<<<TILE_BLKS, 256>>>(W2, b2, out);
}

// round 12
// speedup vs baseline: 2.1055x; 1.0843x over previous
#include <cuda_runtime.h>

#define N_NODES 50000
#define N_EDGES 800000
#define IN_F 96
#define HID 64
#define N_CLS 32

#define PAD 64                 // bucket capacity; mean degree 16, P(>=64) ~ 1e-20
#define FILL_BLKS ((N_EDGES + 255) / 256)          // 3125
#define GEMM1_BLKS ((N_NODES + 31) / 32)           // 1563

// ---------------------------------------------------------------------------
// Scratch. g_cnt is zero at entry of every launch: BSS-zeroed at load, and
// kernel 3 (the last consumer) resets it each execution -> deterministic
// graph replays with no memset pass.
// ---------------------------------------------------------------------------
__device__ __align__(256) int   g_cnt [N_NODES];           // per-dst cursors
__device__ __align__(256) int   g_srcs[N_NODES * PAD];     // 12.8 MB buckets
__device__ __align__(256) float g_p1  [N_NODES * HID];     // x @ W1
__device__ __align__(256) float g_p2  [N_NODES * N_CLS];   // h @ W2

// ===========================================================================
// K1: (a) bucket-fill: g_srcs[dst*PAD + cursor++] = src   (edge-parallel)
//     (b) pre1 GEMM:   g_p1 = x @ W1                      (independent work)
// Fused so the fill's atomic latency hides under the FMA-bound GEMM.
// ===========================================================================
__global__ __launch_bounds__(256) void k1_fill_gemm1(
    const float* __restrict__ x, const int* __restrict__ ei,
    const float* __restrict__ W1)
{
    if (blockIdx.x < FILL_BLKS) {
        int e = blockIdx.x * 256 + threadIdx.x;
        if (e < N_EDGES) {
            int d = ei[N_EDGES + e];
            int p = atomicAdd(&g_cnt[d], 1);
            if (p < PAD) g_srcs[d * PAD + p] = ei[e];
        }
        return;
    }

    // ---- GEMM part: 32 rows/block, thread -> (col c, 8 rows) ----
    __shared__ float As[32][100];          // stride 100 floats = 400 B (16B-aligned)
    __shared__ float Ws[IN_F * HID];       // 24 KB
    int tid  = threadIdx.x;
    int base = (blockIdx.x - FILL_BLKS) * 32;

    for (int i = tid; i < IN_F * HID; i += 256) Ws[i] = W1[i];
    for (int i = tid; i < 32 * IN_F; i += 256) {
        int r = i / IN_F, c = i % IN_F;
        int row = base + r;
        As[r][c] = (row < N_NODES) ? x[(size_t)row * IN_F + c] : 0.f;
    }
    __syncthreads();

    int c  = tid & 63;
    int rb = tid >> 6;                     // 0..3, 8 rows each
    float acc[8];
#pragma unroll
    for (int r = 0; r < 8; r++) acc[r] = 0.f;

#pragma unroll
    for (int kc = 0; kc < IN_F / 4; kc++) {
        int k = kc * 4;
        float w0 = Ws[(k + 0) * HID + c];
        float w1 = Ws[(k + 1) * HID + c];
        float w2 = Ws[(k + 2) * HID + c];
        float w3 = Ws[(k + 3) * HID + c];
#pragma unroll
        for (int r = 0; r < 8; r++) {
            float4 a = *reinterpret_cast<const float4*>(&As[rb * 8 + r][k]);
            acc[r] = fmaf(a.x, w0, fmaf(a.y, w1, fmaf(a.z, w2, fmaf(a.w, w3, acc[r]))));
        }
    }
#pragma unroll
    for (int r = 0; r < 8; r++) {
        int row = base + rb * 8 + r;
        if (row < N_NODES) g_p1[(size_t)row * HID + c] = acc[r];
    }
}

// ===========================================================================
// K2: agg1 = gather g_p1 by bucket, + b1, relu  -> smem tile,
//     then block GEMM tile @ W2 -> g_p2.   (h never hits global memory)
// 32 nodes/block; warp aggregates 4 nodes (float2 per lane = 64-wide row).
// ===========================================================================
__global__ __launch_bounds__(256) void k2_agg1_gemm2(
    const float* __restrict__ b1, const float* __restrict__ W2)
{
    __shared__ float As[32][68];           // 68 floats = 272 B row (16B-aligned!)
    __shared__ float Ws[HID * N_CLS];      // 8 KB
    __shared__ float bs[HID];

    int tid  = threadIdx.x;
    int warp = tid >> 5, lane = tid & 31;
    int base = blockIdx.x * 32;

    for (int i = tid; i < HID * N_CLS; i += 256) Ws[i] = W2[i];
    if (tid < HID) bs[tid] = b1[tid];

    for (int i = 0; i < 4; i++) {
        int r = warp * 4 + i;
        int node = base + r;
        float ax = 0.f, ay = 0.f;
        if (node < N_NODES) {
            int cnt = g_cnt[node];
            if (cnt > PAD) cnt = PAD;
            int bofs = node * PAD;
            int i0 = (lane < cnt)      ? g_srcs[bofs + lane]      : 0;
            int i1 = (lane + 32 < cnt) ? g_srcs[bofs + lane + 32] : 0;
            for (int j = 0; j < cnt; j++) {
                int s = __shfl_sync(0xffffffffu, (j < 32) ? i0 : i1, j & 31);
                float2 v = *reinterpret_cast<const float2*>(
                    g_p1 + (size_t)s * HID + 2 * lane);
                ax += v.x; ay += v.y;
            }
        }
        As[r][2 * lane]     = fmaxf(ax + bs[2 * lane], 0.f);
        As[r][2 * lane + 1] = fmaxf(ay + bs[2 * lane + 1], 0.f);
    }
    __syncthreads();

    // ---- GEMM 32x64 @ 64x32: thread -> (class c = lane, 4 rows) ----
    // All lanes of a warp read the same As float4 -> smem broadcast (N=1).
    int c  = lane;
    int rb = warp;                          // 0..7
    float acc[4];
#pragma unroll
    for (int r = 0; r < 4; r++) acc[r] = 0.f;

#pragma unroll
    for (int kc = 0; kc < HID / 4; kc++) {
        int k = kc * 4;
        float w0 = Ws[(k + 0) * N_CLS + c];
        float w1 = Ws[(k + 1) * N_CLS + c];
        float w2 = Ws[(k + 2) * N_CLS + c];
        float w3 = Ws[(k + 3) * N_CLS + c];
#pragma unroll
        for (int r = 0; r < 4; r++) {
            float4 a = *reinterpret_cast<const float4*>(&As[rb * 4 + r][k]);
            acc[r] = fmaf(a.x, w0, fmaf(a.y, w1, fmaf(a.z, w2, fmaf(a.w, w3, acc[r]))));
        }
    }
#pragma unroll
    for (int r = 0; r < 4; r++) {
        int row = base + rb * 4 + r;
        if (row < N_NODES) g_p2[(size_t)row * N_CLS + c] = acc[r];
    }
}

// ===========================================================================
// K3: agg2 = gather g_p2 by bucket, + b2, warp log_softmax -> out.
// Warp per node (lane == class). Resets g_cnt for the next graph replay.
// ===========================================================================
__global__ __launch_bounds__(256) void k3_agg2_softmax(
    const float* __restrict__ b2, float* __restrict__ out)
{
    int tid  = threadIdx.x;
    int warp = tid >> 5, lane = tid & 31;
    int node = blockIdx.x * 8 + warp;
    if (node >= N_NODES) return;

    int cnt = g_cnt[node];
    if (cnt > PAD) cnt = PAD;
    int bofs = node * PAD;
    int i0 = (lane < cnt)      ? g_srcs[bofs + lane]      : 0;
    int i1 = (lane + 32 < cnt) ? g_srcs[bofs + lane + 32] : 0;

    float acc = 0.f;
    for (int j = 0; j < cnt; j++) {
        int s = __shfl_sync(0xffffffffu, (j < 32) ? i0 : i1, j & 31);
        acc += g_p2[(size_t)s * N_CLS + lane];
    }
    if (lane == 0) g_cnt[node] = 0;        // restore zero-cursor invariant

    float v = acc + b2[lane];
    float m = v;
#pragma unroll
    for (int o = 16; o; o >>= 1) m = fmaxf(m, __shfl_xor_sync(0xffffffffu, m, o));
    float e = __expf(v - m);
    float s = e;
#pragma unroll
    for (int o = 16; o; o >>= 1) s += __shfl_xor_sync(0xffffffffu, s, o);
    out[(size_t)node * N_CLS + lane] = (v - m) - __logf(s);
}

// ---------------------------------------------------------------------------
extern "C" void kernel_launch(void* const* d_in, const int* in_sizes, int n_in,
                              void* d_out, int out_size)
{
    const float* x  = (const float*)d_in[0];
    const int*   ei = (const int*)d_in[1];   // int32 edge index (JAX x64 off)
    const float* W1 = (const float*)d_in[2];
    const float* b1 = (const float*)d_in[3];
    const float* W2 = (const float*)d_in[4];
    const float* b2 = (const float*)d_in[5];
    float* out = (float*)d_out;

    k1_fill_gemm1  <<<FILL_BLKS + GEMM1_BLKS, 256>>>(x, ei, W1);
    k2_agg1_gemm2  <<<GEMM1_BLKS, 256>>>(b1, W2);
    k3_agg2_softmax<<<(N_NODES + 7) / 8, 256>>>(b2, out);
}

// round 15
// speedup vs baseline: 2.2085x; 1.0489x over previous
#include <cuda_runtime.h>

#define N_NODES 50000
#define N_EDGES 800000
#define IN_F 96
#define HID 64
#define N_CLS 32

#define PAD 64                 // bucket capacity; mean degree 16, P(>=64) ~ 1e-20
#define K1_BLOCKS 1563         // covers 1563*512=800256 edges AND 1563*32=50016 rows

// ---------------------------------------------------------------------------
// Scratch. g_cnt is zero at entry of every launch: BSS-zeroed at load, and
// kernel 3 (the last consumer) resets it each execution -> deterministic
// graph replays with no memset pass.
// ---------------------------------------------------------------------------
__device__ __align__(256) int   g_cnt [N_NODES];           // per-dst cursors
__device__ __align__(256) int   g_srcs[N_NODES * PAD];     // 12.8 MB buckets
__device__ __align__(256) float g_p1  [N_NODES * HID];     // x @ W1
__device__ __align__(256) float g_p2  [N_NODES * N_CLS];   // h @ W2

// ===========================================================================
// K1: warp-specialized fusion.
//   warps 0-3  (128 thr): bucket-fill of this block's 512 edges
//                         (atomic-latency-bound -> stalls donate issue slots)
//   warps 4-11 (256 thr): pre1 GEMM  g_p1[base..base+31] = x @ W1
// Fill warps exit early; bar.sync treats exited threads as arrived (sm_70+).
// ===========================================================================
__global__ __launch_bounds__(384) void k1_fill_gemm1(
    const float* __restrict__ x, const int* __restrict__ ei,
    const float* __restrict__ W1)
{
    __shared__ float As[32][100];          // stride 100 floats = 400 B (16B-aligned)
    __shared__ float Ws[IN_F * HID];       // 24 KB
    int tid = threadIdx.x;

    if (tid < 128) {
        // ---- fill part: 4 edges per thread, stride-128 coalesced ----
        int ebase = blockIdx.x * 512;
#pragma unroll
        for (int k = 0; k < 4; k++) {
            int e = ebase + k * 128 + tid;
            if (e < N_EDGES) {
                int d = ei[N_EDGES + e];
                int p = atomicAdd(&g_cnt[d], 1);
                if (p < PAD) g_srcs[d * PAD + p] = ei[e];
            }
        }
        return;
    }

    // ---- GEMM part: 32 rows/block, thread -> (col c, 8 rows) ----
    int gtid = tid - 128;                  // 0..255
    int base = blockIdx.x * 32;

    for (int i = gtid; i < IN_F * HID; i += 256) Ws[i] = W1[i];
    for (int i = gtid; i < 32 * IN_F; i += 256) {
        int r = i / IN_F, c = i % IN_F;
        int row = base + r;
        As[r][c] = (row < N_NODES) ? x[(size_t)row * IN_F + c] : 0.f;
    }
    __syncthreads();

    int c  = gtid & 63;
    int rb = gtid >> 6;                    // 0..3, 8 rows each
    float acc[8];
#pragma unroll
    for (int r = 0; r < 8; r++) acc[r] = 0.f;

#pragma unroll
    for (int kc = 0; kc < IN_F / 4; kc++) {
        int k = kc * 4;
        float w0 = Ws[(k + 0) * HID + c];
        float w1 = Ws[(k + 1) * HID + c];
        float w2 = Ws[(k + 2) * HID + c];
        float w3 = Ws[(k + 3) * HID + c];
#pragma unroll
        for (int r = 0; r < 8; r++) {
            float4 a = *reinterpret_cast<const float4*>(&As[rb * 8 + r][k]);
            acc[r] = fmaf(a.x, w0, fmaf(a.y, w1, fmaf(a.z, w2, fmaf(a.w, w3, acc[r]))));
        }
    }
#pragma unroll
    for (int r = 0; r < 8; r++) {
        int row = base + rb * 8 + r;
        if (row < N_NODES) g_p1[(size_t)row * HID + c] = acc[r];
    }
}

// ===========================================================================
// K2: agg1 = gather g_p1 by bucket, + b1, relu  -> smem tile,
//     then block GEMM tile @ W2 -> g_p2.   (h never hits global memory)
// 32 nodes/block; warp aggregates 4 nodes (float2 per lane = 64-wide row).
// ===========================================================================
__global__ __launch_bounds__(256) void k2_agg1_gemm2(
    const float* __restrict__ b1, const float* __restrict__ W2)
{
    __shared__ float As[32][68];           // 68 floats = 272 B row (16B-aligned)
    __shared__ float Ws[HID * N_CLS];      // 8 KB
    __shared__ float bs[HID];

    int tid  = threadIdx.x;
    int warp = tid >> 5, lane = tid & 31;
    int base = blockIdx.x * 32;

    for (int i = tid; i < HID * N_CLS; i += 256) Ws[i] = W2[i];
    if (tid < HID) bs[tid] = b1[tid];

    for (int i = 0; i < 4; i++) {
        int r = warp * 4 + i;
        int node = base + r;
        float ax = 0.f, ay = 0.f;
        if (node < N_NODES) {
            int cnt = g_cnt[node];
            if (cnt > PAD) cnt = PAD;
            int bofs = node * PAD;
            int i0 = (lane < cnt)      ? g_srcs[bofs + lane]      : 0;
            int i1 = (lane + 32 < cnt) ? g_srcs[bofs + lane + 32] : 0;
            for (int j = 0; j < cnt; j++) {
                int s = __shfl_sync(0xffffffffu, (j < 32) ? i0 : i1, j & 31);
                float2 v = *reinterpret_cast<const float2*>(
                    g_p1 + (size_t)s * HID + 2 * lane);
                ax += v.x; ay += v.y;
            }
        }
        As[r][2 * lane]     = fmaxf(ax + bs[2 * lane], 0.f);
        As[r][2 * lane + 1] = fmaxf(ay + bs[2 * lane + 1], 0.f);
    }
    __syncthreads();

    // ---- GEMM 32x64 @ 64x32: thread -> (class c = lane, 4 rows) ----
    int c  = lane;
    int rb = warp;                          // 0..7
    float acc[4];
#pragma unroll
    for (int r = 0; r < 4; r++) acc[r] = 0.f;

#pragma unroll
    for (int kc = 0; kc < HID / 4; kc++) {
        int k = kc * 4;
        float w0 = Ws[(k + 0) * N_CLS + c];
        float w1 = Ws[(k + 1) * N_CLS + c];
        float w2 = Ws[(k + 2) * N_CLS + c];
        float w3 = Ws[(k + 3) * N_CLS + c];
#pragma unroll
        for (int r = 0; r < 4; r++) {
            float4 a = *reinterpret_cast<const float4*>(&As[rb * 4 + r][k]);
            acc[r] = fmaf(a.x, w0, fmaf(a.y, w1, fmaf(a.z, w2, fmaf(a.w, w3, acc[r]))));
        }
    }
#pragma unroll
    for (int r = 0; r < 4; r++) {
        int row = base + rb * 4 + r;
        if (row < N_NODES) g_p2[(size_t)row * N_CLS + c] = acc[r];
    }
}

// ===========================================================================
// K3: agg2 = gather g_p2 by bucket, + b2, warp log_softmax -> out.
// Warp per node (lane == class). Resets g_cnt for the next graph replay.
// ===========================================================================
__global__ __launch_bounds__(256) void k3_agg2_softmax(
    const float* __restrict__ b2, float* __restrict__ out)
{
    int tid  = threadIdx.x;
    int warp = tid >> 5, lane = tid & 31;
    int node = blockIdx.x * 8 + warp;
    if (node >= N_NODES) return;

    int cnt = g_cnt[node];
    if (cnt > PAD) cnt = PAD;
    int bofs = node * PAD;
    int i0 = (lane < cnt)      ? g_srcs[bofs + lane]      : 0;
    int i1 = (lane + 32 < cnt) ? g_srcs[bofs + lane + 32] : 0;

    float acc = 0.f;
    for (int j = 0; j < cnt; j++) {
        int s = __shfl_sync(0xffffffffu, (j < 32) ? i0 : i1, j & 31);
        acc += g_p2[(size_t)s * N_CLS + lane];
    }
    if (lane == 0) g_cnt[node] = 0;        // restore zero-cursor invariant

    float v = acc + b2[lane];
    float m = v;
#pragma unroll
    for (int o = 16; o; o >>= 1) m = fmaxf(m, __shfl_xor_sync(0xffffffffu, m, o));
    float e = __expf(v - m);
    float s = e;
#pragma unroll
    for (int o = 16; o; o >>= 1) s += __shfl_xor_sync(0xffffffffu, s, o);
    out[(size_t)node * N_CLS + lane] = (v - m) - __logf(s);
}

// ---------------------------------------------------------------------------
extern "C" void kernel_launch(void* const* d_in, const int* in_sizes, int n_in,
                              void* d_out, int out_size)
{
    const float* x  = (const float*)d_in[0];
    const int*   ei = (const int*)d_in[1];   // int32 edge index (JAX x64 off)
    const float* W1 = (const float*)d_in[2];
    const float* b1 = (const float*)d_in[3];
    const float* W2 = (const float*)d_in[4];
    const float* b2 = (const float*)d_in[5];
    float* out = (float*)d_out;

    k1_fill_gemm1  <<<K1_BLOCKS, 384>>>(x, ei, W1);
    k2_agg1_gemm2  <<<K1_BLOCKS, 256>>>(b1, W2);
    k3_agg2_softmax<<<(N_NODES + 7) / 8, 256>>>(b2, out);
}